// round 11
// baseline (speedup 1.0000x reference)
#include <cuda_runtime.h>
#include <cuda_fp16.h>
#include <stdint.h>
#include <math.h>

#define HDIM    4096
#define NEXP    256
#define KC      32
#define NCHUNK  128
#define MTILE   64
#define TOPK    8

#define A_SP    4096                 // one A split tile: 64 rows x 64B
#define B_SP    16384                // one B split tile: 256 rows x 64B
#define A_BYTES (2*A_SP)             // 8192
#define B_BYTES (2*B_SP)             // 32768
#define STAGE   (A_BYTES + B_BYTES)  // 40960
#define SM_BASE 1024
#define SMEM_BYTES (SM_BASE + 2*STAGE)  // 82944  -> 2 CTAs/SM
#define LSTR 260

// Pre-split, pre-swizzled W (fp16 h + m*4096): [chunk32][2 splits][16KB]
__device__ __align__(128) uint8_t g_wt[(size_t)NCHUNK * B_BYTES];

__device__ __forceinline__ uint32_t smem_u32(const void* p) {
    uint32_t a;
    asm("{ .reg .u64 t; cvta.to.shared.u64 t, %1; cvt.u32.u64 %0, t; }" : "=r"(a) : "l"(p));
    return a;
}
__device__ __forceinline__ uint32_t swz64(uint32_t o) { return o ^ ((o >> 3) & 0x30); }

__device__ __forceinline__ uint32_t packh(float lo, float hi) {
    __half2 h = __floats2half2_rn(lo, hi);   // .x = lo (low 16) = even k elem
    return *(uint32_t*)&h;
}
// x = h + m*2^-12, m kept fp16-normal; residual <= ~2^-24 |x|
__device__ __forceinline__ void split2(float x0, float x1, uint32_t& h, uint32_t& m) {
    h = packh(x0, x1);
    __half2 hh = *(__half2*)&h;
    float h0 = __low2float(hh), h1 = __high2float(hh);
    m = packh((x0 - h0) * 4096.0f, (x1 - h1) * 4096.0f);
}

__device__ __forceinline__ void mbar_init(uint32_t a, uint32_t c) {
    asm volatile("mbarrier.init.shared.b64 [%0], %1;" :: "r"(a), "r"(c) : "memory");
}
__device__ __forceinline__ void mbar_expect_tx(uint32_t a, uint32_t b) {
    asm volatile("mbarrier.arrive.expect_tx.shared.b64 _, [%0], %1;" :: "r"(a), "r"(b) : "memory");
}
__device__ __forceinline__ void mbar_wait(uint32_t a, uint32_t ph) {
    uint32_t done;
    asm volatile("{\n\t.reg .pred p;\n\t"
                 "mbarrier.try_wait.parity.acquire.cta.shared::cta.b64 p, [%1], %2;\n\t"
                 "selp.b32 %0,1,0,p;\n\t}" : "=r"(done) : "r"(a), "r"(ph) : "memory");
    if (!done) {
        asm volatile("{\n\t.reg .pred P;\n"
                     "W0_%=:\n\t"
                     "mbarrier.try_wait.parity.acquire.cta.shared::cta.b64 P, [%0], %1, 0x989680;\n\t"
                     "@P bra W1_%=;\n\t"
                     "bra W0_%=;\n"
                     "W1_%=:\n\t}" :: "r"(a), "r"(ph) : "memory");
    }
}
__device__ __forceinline__ void bulk_cp(uint32_t dst, const void* src, uint32_t bytes, uint32_t mbar) {
    asm volatile("cp.async.bulk.shared::cluster.global.mbarrier::complete_tx::bytes "
                 "[%0], [%1], %2, [%3];"
                 :: "r"(dst), "l"(src), "r"(bytes), "r"(mbar) : "memory");
}

#define LDSM4(r, addr)                                                           \
    asm volatile("ldmatrix.sync.aligned.m8n8.x4.shared.b16 {%0,%1,%2,%3}, [%4];" \
        : "=r"((r)[0]), "=r"((r)[1]), "=r"((r)[2]), "=r"((r)[3]) : "r"(addr))

#define MMA_ACC(c, a, b0v, b1v)                                                  \
    asm volatile("mma.sync.aligned.m16n8k16.row.col.f32.f16.f16.f32 "            \
        "{%0,%1,%2,%3}, {%4,%5,%6,%7}, {%8,%9}, {%0,%1,%2,%3};"                  \
        : "+f"((c)[0]), "+f"((c)[1]), "+f"((c)[2]), "+f"((c)[3])                 \
        : "r"((a)[0]), "r"((a)[1]), "r"((a)[2]), "r"((a)[3]), "r"(b0v), "r"(b1v))

#define MMA_NEW(c, a, b0v, b1v)                                                  \
    asm volatile("mma.sync.aligned.m16n8k16.row.col.f32.f16.f16.f32 "            \
        "{%0,%1,%2,%3}, {%4,%5,%6,%7}, {%8,%9}, {%10,%10,%10,%10};"              \
        : "=f"((c)[0]), "=f"((c)[1]), "=f"((c)[2]), "=f"((c)[3])                 \
        : "r"((a)[0]), "r"((a)[1]), "r"((a)[2]), "r"((a)[3]), "r"(b0v), "r"(b1v),\
          "f"(0.0f))

// ---------------- W pre-split kernel: grid=128 k32-chunks, 256 thr = experts ---
__global__ void __launch_bounds__(256) wprep_kernel(const float* __restrict__ w) {
    const int c = blockIdx.x;
    const int e = threadIdx.x;
    const float4* src = (const float4*)(w + (size_t)e * HDIM + c * KC);
    float xv[32];
    #pragma unroll
    for (int i = 0; i < 8; i++) {
        float4 f = src[i];
        xv[i*4+0]=f.x; xv[i*4+1]=f.y; xv[i*4+2]=f.z; xv[i*4+3]=f.w;
    }
    uint32_t hh[16], mm_[16];
    #pragma unroll
    for (int j = 0; j < 16; j++) split2(xv[2*j], xv[2*j+1], hh[j], mm_[j]);
    uint8_t* base = g_wt + (size_t)c * B_BYTES;
    #pragma unroll
    for (int b = 0; b < 4; b++) {
        uint32_t so = swz64((uint32_t)e * 64 + b * 16);
        *(uint4*)(base + 0*B_SP + so) = make_uint4(hh[4*b],hh[4*b+1],hh[4*b+2],hh[4*b+3]);
        *(uint4*)(base + 1*B_SP + so) = make_uint4(mm_[4*b],mm_[4*b+1],mm_[4*b+2],mm_[4*b+3]);
    }
}

// ---------------- main kernel: grid = T/64, 256 threads, 2 CTAs/SM ------------
__global__ void __launch_bounds__(256, 2)
moe_gate_mma(const float* __restrict__ x, float* __restrict__ out, int T) {
    extern __shared__ __align__(1024) uint8_t smem[];
    const uint32_t sbase = smem_u32(smem);
    const int tid  = threadIdx.x;
    const int wid  = tid >> 5;
    const int lane = tid & 31;
    const int row_base = blockIdx.x * MTILE;

    if (tid == 0) { mbar_init(sbase + 16, 1); mbar_init(sbase + 24, 1); }

    // A staging: thread -> row = tid/4 (0..63), 8 k-elems at (tid%4)*8
    const int arow = tid >> 2;
    const int aq   = tid & 3;
    const float* xrow = x + (size_t)(row_base + arow) * HDIM + aq * 8;
    const uint32_t a_sts = swz64((uint32_t)arow * 64 + aq * 16);

    // warp tile: 32M x 64N  (8 warps = 2M x 4N)
    const int wm = wid & 1, wn = wid >> 1;
    const int m0 = wm * 32, n0 = wn * 64;

    // swizzled ldmatrix offsets (ks = k16 step within KC=32)
    uint32_t aoff[2][2], boff[2][4];
    {
        uint32_t a_row = (uint32_t)(m0 + (lane & 15));
        uint32_t a_kh  = (uint32_t)(lane >> 4) * 16;
        uint32_t b_n   = (uint32_t)(n0 + (lane & 7) + ((lane >> 4) & 1) * 8);
        uint32_t b_kh  = (uint32_t)((lane >> 3) & 1) * 16;
        #pragma unroll
        for (int ks = 0; ks < 2; ks++) {
            #pragma unroll
            for (int mi = 0; mi < 2; mi++)
                aoff[ks][mi] = swz64((a_row + mi*16) * 64 + ks*32 + a_kh);
            #pragma unroll
            for (int nb = 0; nb < 4; nb++)
                boff[ks][nb] = swz64((b_n + nb*16) * 64 + ks*32 + b_kh);
        }
    }

    float master[2][8][4];   // fp32-RN sum of hh products
    float winc[2][8][4];     // hm+mh chained window (x4096)
    #pragma unroll
    for (int mi = 0; mi < 2; mi++)
        #pragma unroll
        for (int j = 0; j < 8; j++)
            #pragma unroll
            for (int q = 0; q < 4; q++)
                { master[mi][j][q] = 0.0f; winc[mi][j][q] = 0.0f; }

    __syncthreads();   // mbarriers visible

    // prologue: stage chunk 0 (A split + TMA B), prefetch x chunk 1
    if (tid == 0) {
        mbar_expect_tx(sbase + 16, B_BYTES);
        bulk_cp(sbase + SM_BASE + A_BYTES, g_wt, B_BYTES, sbase + 16);
    }
    {
        float4 f0 = *(const float4*)(xrow);
        float4 f1 = *(const float4*)(xrow + 4);
        uint32_t h[4], m[4];
        split2(f0.x, f0.y, h[0], m[0]); split2(f0.z, f0.w, h[1], m[1]);
        split2(f1.x, f1.y, h[2], m[2]); split2(f1.z, f1.w, h[3], m[3]);
        *(uint4*)(smem + SM_BASE + 0*A_SP + a_sts) = make_uint4(h[0],h[1],h[2],h[3]);
        *(uint4*)(smem + SM_BASE + 1*A_SP + a_sts) = make_uint4(m[0],m[1],m[2],m[3]);
    }
    float4 xp0 = *(const float4*)(xrow + KC);
    float4 xp1 = *(const float4*)(xrow + KC + 4);
    __syncthreads();

    for (int i = 0; i < NCHUNK; i++) {
        const int s = i & 1;
        const uint32_t stoff = SM_BASE + (uint32_t)s * STAGE;

        mbar_wait(sbase + 16 + 8*s, (i >> 1) & 1);

        if (i < NCHUNK - 1) {
            const uint32_t nstoff = SM_BASE + (uint32_t)(s ^ 1) * STAGE;
            if (tid == 0) {
                mbar_expect_tx(sbase + 16 + 8*(s^1), B_BYTES);
                bulk_cp(sbase + nstoff + A_BYTES, g_wt + (size_t)(i+1) * B_BYTES,
                        B_BYTES, sbase + 16 + 8*(s^1));
            }
            uint32_t h[4], m[4];
            split2(xp0.x, xp0.y, h[0], m[0]); split2(xp0.z, xp0.w, h[1], m[1]);
            split2(xp1.x, xp1.y, h[2], m[2]); split2(xp1.z, xp1.w, h[3], m[3]);
            *(uint4*)(smem + nstoff + 0*A_SP + a_sts) = make_uint4(h[0],h[1],h[2],h[3]);
            *(uint4*)(smem + nstoff + 1*A_SP + a_sts) = make_uint4(m[0],m[1],m[2],m[3]);
            if (i < NCHUNK - 2) {
                xp0 = *(const float4*)(xrow + (size_t)(i+2) * KC);
                xp1 = *(const float4*)(xrow + (size_t)(i+2) * KC + 4);
            }
        }

        // ---- compute chunk i: 2 k16 steps (hh drained, mh+hm chained) ----
        const uint32_t Ab = sbase + stoff;
        const uint32_t Bb = sbase + stoff + A_BYTES;
        #pragma unroll
        for (int ks = 0; ks < 2; ks++) {
            uint32_t Bf[4][4], Ah[2][4], Am[2][4];
            #pragma unroll
            for (int nb = 0; nb < 4; nb++)
                LDSM4(Bf[nb], Bb + boff[ks][nb]);            // B_h
            #pragma unroll
            for (int mi = 0; mi < 2; mi++)
                LDSM4(Ah[mi], Ab + aoff[ks][mi]);            // A_h
            #pragma unroll
            for (int mi = 0; mi < 2; mi++)
                LDSM4(Am[mi], Ab + A_SP + aoff[ks][mi]);     // A_m

            // hh: fresh C per MMA, immediate fp32-RN drain
            #pragma unroll
            for (int mi = 0; mi < 2; mi++) {
                float wh[8][4];
                #pragma unroll
                for (int nb = 0; nb < 4; nb++) {
                    MMA_NEW(wh[nb*2+0], Ah[mi], Bf[nb][0], Bf[nb][1]);
                    MMA_NEW(wh[nb*2+1], Ah[mi], Bf[nb][2], Bf[nb][3]);
                }
                #pragma unroll
                for (int j = 0; j < 8; j++)
                    #pragma unroll
                    for (int q = 0; q < 4; q++)
                        master[mi][j][q] += wh[j][q];
            }
            // mh: A_m x B_h into chained window
            #pragma unroll
            for (int mi = 0; mi < 2; mi++)
                #pragma unroll
                for (int nb = 0; nb < 4; nb++) {
                    MMA_ACC(winc[mi][nb*2+0], Am[mi], Bf[nb][0], Bf[nb][1]);
                    MMA_ACC(winc[mi][nb*2+1], Am[mi], Bf[nb][2], Bf[nb][3]);
                }
            // hm: B_m reuses Bf
            #pragma unroll
            for (int nb = 0; nb < 4; nb++)
                LDSM4(Bf[nb], Bb + B_SP + boff[ks][nb]);
            #pragma unroll
            for (int mi = 0; mi < 2; mi++)
                #pragma unroll
                for (int nb = 0; nb < 4; nb++) {
                    MMA_ACC(winc[mi][nb*2+0], Ah[mi], Bf[nb][0], Bf[nb][1]);
                    MMA_ACC(winc[mi][nb*2+1], Ah[mi], Bf[nb][2], Bf[nb][3]);
                }
        }
        __syncthreads();
    }

    // combine: logits = master + winc * 2^-12
    const float CS = 1.0f / 4096.0f;
    #pragma unroll
    for (int mi = 0; mi < 2; mi++)
        #pragma unroll
        for (int j = 0; j < 8; j++)
            #pragma unroll
            for (int q = 0; q < 4; q++)
                master[mi][j][q] = fmaf(winc[mi][j][q], CS, master[mi][j][q]);

    // ---- epilogue: dump logits to smem, per-thread top-8 ----
    float* lg = (float*)(smem + SM_BASE);
    #pragma unroll
    for (int mi = 0; mi < 2; mi++)
        #pragma unroll
        for (int j = 0; j < 8; j++) {
            int r = m0 + mi*16 + (lane >> 2);
            int cc = n0 + j*8 + 2*(lane & 3);
            *(float2*)&lg[(size_t)r * LSTR + cc]       = make_float2(master[mi][j][0], master[mi][j][1]);
            *(float2*)&lg[(size_t)(r + 8) * LSTR + cc] = make_float2(master[mi][j][2], master[mi][j][3]);
        }
    __syncthreads();

    if (tid < MTILE) {
        const int row = row_base + tid;
        float tv[TOPK]; int ti[TOPK];
        #pragma unroll
        for (int t = 0; t < TOPK; t++) { tv[t] = -INFINITY; ti[t] = 0x7fffffff; }
        const float* lr = &lg[(size_t)tid * LSTR];
        for (int g = 0; g < 64; g++) {
            float4 v4 = *(const float4*)(lr + g * 4);
            float vs[4] = {v4.x, v4.y, v4.z, v4.w};
            #pragma unroll
            for (int q = 0; q < 4; q++) {
                float v = vs[q];
                if (v > tv[TOPK-1]) {
                    tv[TOPK-1] = v; ti[TOPK-1] = g*4 + q;
                    #pragma unroll
                    for (int t = TOPK-1; t > 0; t--) {
                        if (tv[t] > tv[t-1]) {
                            float fv = tv[t]; tv[t] = tv[t-1]; tv[t-1] = fv;
                            int   fi = ti[t]; ti[t] = ti[t-1]; ti[t-1] = fi;
                        }
                    }
                }
            }
        }
        // Z cancels under top-k renorm: w_t = 2.5 * exp(v_t - mx) / sum
        float e[TOPK], ssum = 0.0f;
        #pragma unroll
        for (int t = 0; t < TOPK; t++) { e[t] = expf(tv[t] - tv[0]); ssum += e[t]; }
        const float scale = 2.5f / ssum;
        const size_t base = (size_t)row * TOPK;
        const size_t wofs = (size_t)T * TOPK;
        #pragma unroll
        for (int t = 0; t < TOPK; t++) {
            out[base + t]        = (float)ti[t];
            out[wofs + base + t] = e[t] * scale;
        }
    }
}

extern "C" void kernel_launch(void* const* d_in, const int* in_sizes, int n_in,
                              void* d_out, int out_size) {
    const float* x = (const float*)d_in[0];
    const float* w = (const float*)d_in[1];
    float* out = (float*)d_out;
    int T = in_sizes[0] / HDIM;   // 16384

    cudaFuncSetAttribute(moe_gate_mma, cudaFuncAttributeMaxDynamicSharedMemorySize, SMEM_BYTES);

    wprep_kernel<<<NCHUNK, 256>>>(w);
    moe_gate_mma<<<T / MTILE, 256, SMEM_BYTES>>>(x, out, T);
}

// round 14
// speedup vs baseline: 1.8939x; 1.8939x over previous
#include <cuda_runtime.h>
#include <cuda_fp16.h>
#include <stdint.h>
#include <math.h>

#define HDIM    4096
#define NEXP    256
#define KC      32
#define NCHUNK  128
#define MTILE   64
#define TOPK    8

#define A_SP    4096                 // one A split tile: 64 rows x 64B
#define B_SP    16384                // one B split tile: 256 rows x 64B
#define A_BYTES (2*A_SP)             // 8192
#define B_BYTES (2*B_SP)             // 32768
#define STAGE   (A_BYTES + B_BYTES)  // 40960
#define SM_BASE 1024
#define SMEM_BYTES (SM_BASE + 2*STAGE)  // 82944
#define LSTR 260

// Pre-split, pre-swizzled W (fp16 h + m*4096): [chunk32][2 splits][16KB]
__device__ __align__(128) uint8_t g_wt[(size_t)NCHUNK * B_BYTES];

__device__ __forceinline__ uint32_t smem_u32(const void* p) {
    uint32_t a;
    asm("{ .reg .u64 t; cvta.to.shared.u64 t, %1; cvt.u32.u64 %0, t; }" : "=r"(a) : "l"(p));
    return a;
}
__device__ __forceinline__ uint32_t swz64(uint32_t o) { return o ^ ((o >> 3) & 0x30); }

__device__ __forceinline__ uint32_t packh(float lo, float hi) {
    __half2 h = __floats2half2_rn(lo, hi);   // .x = lo (low 16) = even k elem
    return *(uint32_t*)&h;
}
// x = h + m*2^-12, m kept fp16-normal; residual <= ~2^-24 |x|
__device__ __forceinline__ void split2(float x0, float x1, uint32_t& h, uint32_t& m) {
    h = packh(x0, x1);
    __half2 hh = *(__half2*)&h;
    float h0 = __low2float(hh), h1 = __high2float(hh);
    m = packh((x0 - h0) * 4096.0f, (x1 - h1) * 4096.0f);
}

__device__ __forceinline__ void mbar_init(uint32_t a, uint32_t c) {
    asm volatile("mbarrier.init.shared.b64 [%0], %1;" :: "r"(a), "r"(c) : "memory");
}
__device__ __forceinline__ void mbar_expect_tx(uint32_t a, uint32_t b) {
    asm volatile("mbarrier.arrive.expect_tx.shared.b64 _, [%0], %1;" :: "r"(a), "r"(b) : "memory");
}
__device__ __forceinline__ void mbar_wait(uint32_t a, uint32_t ph) {
    uint32_t done;
    asm volatile("{\n\t.reg .pred p;\n\t"
                 "mbarrier.try_wait.parity.acquire.cta.shared::cta.b64 p, [%1], %2;\n\t"
                 "selp.b32 %0,1,0,p;\n\t}" : "=r"(done) : "r"(a), "r"(ph) : "memory");
    if (!done) {
        asm volatile("{\n\t.reg .pred P;\n"
                     "W0_%=:\n\t"
                     "mbarrier.try_wait.parity.acquire.cta.shared::cta.b64 P, [%0], %1, 0x989680;\n\t"
                     "@P bra W1_%=;\n\t"
                     "bra W0_%=;\n"
                     "W1_%=:\n\t}" :: "r"(a), "r"(ph) : "memory");
    }
}
__device__ __forceinline__ void bulk_cp(uint32_t dst, const void* src, uint32_t bytes, uint32_t mbar) {
    asm volatile("cp.async.bulk.shared::cluster.global.mbarrier::complete_tx::bytes "
                 "[%0], [%1], %2, [%3];"
                 :: "r"(dst), "l"(src), "r"(bytes), "r"(mbar) : "memory");
}

#define LDSM4(r, addr)                                                           \
    asm volatile("ldmatrix.sync.aligned.m8n8.x4.shared.b16 {%0,%1,%2,%3}, [%4];" \
        : "=r"((r)[0]), "=r"((r)[1]), "=r"((r)[2]), "=r"((r)[3]) : "r"(addr))

#define MMA_ACC(c, a, b0v, b1v)                                                  \
    asm volatile("mma.sync.aligned.m16n8k16.row.col.f32.f16.f16.f32 "            \
        "{%0,%1,%2,%3}, {%4,%5,%6,%7}, {%8,%9}, {%0,%1,%2,%3};"                  \
        : "+f"((c)[0]), "+f"((c)[1]), "+f"((c)[2]), "+f"((c)[3])                 \
        : "r"((a)[0]), "r"((a)[1]), "r"((a)[2]), "r"((a)[3]), "r"(b0v), "r"(b1v))

#define MMA_NEW(c, a, b0v, b1v)                                                  \
    asm volatile("mma.sync.aligned.m16n8k16.row.col.f32.f16.f16.f32 "            \
        "{%0,%1,%2,%3}, {%4,%5,%6,%7}, {%8,%9}, {%10,%10,%10,%10};"              \
        : "=f"((c)[0]), "=f"((c)[1]), "=f"((c)[2]), "=f"((c)[3])                 \
        : "r"((a)[0]), "r"((a)[1]), "r"((a)[2]), "r"((a)[3]), "r"(b0v), "r"(b1v),\
          "f"(0.0f))

// ---------------- W pre-split kernel: grid=128 k32-chunks, 256 thr = experts ---
__global__ void __launch_bounds__(256) wprep_kernel(const float* __restrict__ w) {
    const int c = blockIdx.x;
    const int e = threadIdx.x;
    const float4* src = (const float4*)(w + (size_t)e * HDIM + c * KC);
    float xv[32];
    #pragma unroll
    for (int i = 0; i < 8; i++) {
        float4 f = src[i];
        xv[i*4+0]=f.x; xv[i*4+1]=f.y; xv[i*4+2]=f.z; xv[i*4+3]=f.w;
    }
    uint32_t hh[16], mm_[16];
    #pragma unroll
    for (int j = 0; j < 16; j++) split2(xv[2*j], xv[2*j+1], hh[j], mm_[j]);
    uint8_t* base = g_wt + (size_t)c * B_BYTES;
    #pragma unroll
    for (int b = 0; b < 4; b++) {
        uint32_t so = swz64((uint32_t)e * 64 + b * 16);
        *(uint4*)(base + 0*B_SP + so) = make_uint4(hh[4*b],hh[4*b+1],hh[4*b+2],hh[4*b+3]);
        *(uint4*)(base + 1*B_SP + so) = make_uint4(mm_[4*b],mm_[4*b+1],mm_[4*b+2],mm_[4*b+3]);
    }
}

// -------- main kernel: grid = T/64, 512 threads (16 warps, warp tile 32x32) ----
__global__ void __launch_bounds__(512, 1)
moe_gate_mma(const float* __restrict__ x, float* __restrict__ out, int T) {
    extern __shared__ __align__(1024) uint8_t smem[];
    const uint32_t sbase = smem_u32(smem);
    const int tid  = threadIdx.x;
    const int wid  = tid >> 5;
    const int lane = tid & 31;
    const int row_base = blockIdx.x * MTILE;

    if (tid == 0) { mbar_init(sbase + 16, 1); mbar_init(sbase + 24, 1); }

    // A staging: thread -> row = tid/8 (0..63), 4 fp32 k-elems at (tid%8)*4
    const int arow = tid >> 3;
    const int aq   = tid & 7;
    const float* xrow = x + (size_t)(row_base + arow) * HDIM + aq * 4;
    const uint32_t a_sts = swz64((uint32_t)arow * 64 + aq * 8);   // 8B per thread

    // warp tile: 32M x 32N  (16 warps = 2M x 8N)
    const int m0 = (wid & 1) * 32;
    const int n0 = (wid >> 1) * 32;

    // swizzled ldmatrix offsets (swizzle applied after adding k-step offset)
    uint32_t aoff[2][2], boff[2][2];
    {
        uint32_t a_row = (uint32_t)(m0 + (lane & 15));
        uint32_t a_kh  = (uint32_t)(lane >> 4) * 16;
        uint32_t b_n   = (uint32_t)(n0 + (lane & 7) + ((lane >> 4) & 1) * 8);
        uint32_t b_kh  = (uint32_t)((lane >> 3) & 1) * 16;
        #pragma unroll
        for (int ks = 0; ks < 2; ks++) {
            #pragma unroll
            for (int mi = 0; mi < 2; mi++)
                aoff[ks][mi] = swz64((a_row + mi*16) * 64 + ks*32 + a_kh);
            #pragma unroll
            for (int nb = 0; nb < 2; nb++)
                boff[ks][nb] = swz64((b_n + nb*16) * 64 + ks*32 + b_kh);
        }
    }

    float master[2][4][4];   // fp32-RN sum of hh products (32 regs)
    float winc[2][4][4];     // hm+mh persistent chained window, x4096 (32 regs)
    #pragma unroll
    for (int mi = 0; mi < 2; mi++)
        #pragma unroll
        for (int j = 0; j < 4; j++)
            #pragma unroll
            for (int q = 0; q < 4; q++)
                { master[mi][j][q] = 0.0f; winc[mi][j][q] = 0.0f; }

    __syncthreads();   // mbarriers visible

    // prologue: stage chunk 0, prefetch x chunk 1
    if (tid == 0) {
        mbar_expect_tx(sbase + 16, B_BYTES);
        bulk_cp(sbase + SM_BASE + A_BYTES, g_wt, B_BYTES, sbase + 16);
    }
    {
        float4 f = *(const float4*)(xrow);
        uint32_t h0, m0_, h1, m1_;
        split2(f.x, f.y, h0, m0_); split2(f.z, f.w, h1, m1_);
        *(uint2*)(smem + SM_BASE + 0*A_SP + a_sts) = make_uint2(h0, h1);
        *(uint2*)(smem + SM_BASE + 1*A_SP + a_sts) = make_uint2(m0_, m1_);
    }
    float4 xp = *(const float4*)(xrow + KC);
    __syncthreads();

    for (int i = 0; i < NCHUNK; i++) {
        const int s = i & 1;
        const uint32_t stoff = SM_BASE + (uint32_t)s * STAGE;

        mbar_wait(sbase + 16 + 8*s, (i >> 1) & 1);

        if (i < NCHUNK - 1) {
            const uint32_t nstoff = SM_BASE + (uint32_t)(s ^ 1) * STAGE;
            if (tid == 0) {
                mbar_expect_tx(sbase + 16 + 8*(s^1), B_BYTES);
                bulk_cp(sbase + nstoff + A_BYTES, g_wt + (size_t)(i+1) * B_BYTES,
                        B_BYTES, sbase + 16 + 8*(s^1));
            }
            uint32_t h0, m0_, h1, m1_;
            split2(xp.x, xp.y, h0, m0_); split2(xp.z, xp.w, h1, m1_);
            *(uint2*)(smem + nstoff + 0*A_SP + a_sts) = make_uint2(h0, h1);
            *(uint2*)(smem + nstoff + 1*A_SP + a_sts) = make_uint2(m0_, m1_);
            if (i < NCHUNK - 2)
                xp = *(const float4*)(xrow + (size_t)(i+2) * KC);
        }

        // ---- compute chunk i: 2 k16 steps (per-element order: hh, mh, hm) ----
        const uint32_t Ab = sbase + stoff;
        const uint32_t Bb = sbase + stoff + A_BYTES;
        #pragma unroll
        for (int ks = 0; ks < 2; ks++) {
            uint32_t Bf[2][4], Ah[2][4], Am[2][4];
            #pragma unroll
            for (int nb = 0; nb < 2; nb++) LDSM4(Bf[nb], Bb + boff[ks][nb]);   // B_h
            #pragma unroll
            for (int mi = 0; mi < 2; mi++) LDSM4(Ah[mi], Ab + aoff[ks][mi]);
            #pragma unroll
            for (int mi = 0; mi < 2; mi++) LDSM4(Am[mi], Ab + A_SP + aoff[ks][mi]);

            // hh: fresh C per MMA, immediate fp32-RN drain (Wc scratch 16 regs)
            #pragma unroll
            for (int mi = 0; mi < 2; mi++) {
                float Wc[4][4];
                #pragma unroll
                for (int nb = 0; nb < 2; nb++) {
                    MMA_NEW(Wc[nb*2+0], Ah[mi], Bf[nb][0], Bf[nb][1]);
                    MMA_NEW(Wc[nb*2+1], Ah[mi], Bf[nb][2], Bf[nb][3]);
                }
                #pragma unroll
                for (int j = 0; j < 4; j++)
                    #pragma unroll
                    for (int q = 0; q < 4; q++)
                        master[mi][j][q] += Wc[j][q];
            }
            // mh: A_m x B_h into persistent chained window
            #pragma unroll
            for (int mi = 0; mi < 2; mi++)
                #pragma unroll
                for (int nb = 0; nb < 2; nb++) {
                    MMA_ACC(winc[mi][nb*2+0], Am[mi], Bf[nb][0], Bf[nb][1]);
                    MMA_ACC(winc[mi][nb*2+1], Am[mi], Bf[nb][2], Bf[nb][3]);
                }
            // hm: B_m reuses Bf regs (B_h dead)
            #pragma unroll
            for (int nb = 0; nb < 2; nb++) LDSM4(Bf[nb], Bb + B_SP + boff[ks][nb]);
            #pragma unroll
            for (int mi = 0; mi < 2; mi++)
                #pragma unroll
                for (int nb = 0; nb < 2; nb++) {
                    MMA_ACC(winc[mi][nb*2+0], Ah[mi], Bf[nb][0], Bf[nb][1]);
                    MMA_ACC(winc[mi][nb*2+1], Ah[mi], Bf[nb][2], Bf[nb][3]);
                }
        }
        __syncthreads();
    }

    // combine: logits = master + winc * 2^-12 (single final fold, as in R7/R10)
    const float CS = 1.0f / 4096.0f;
    #pragma unroll
    for (int mi = 0; mi < 2; mi++)
        #pragma unroll
        for (int j = 0; j < 4; j++)
            #pragma unroll
            for (int q = 0; q < 4; q++)
                master[mi][j][q] = fmaf(winc[mi][j][q], CS, master[mi][j][q]);

    // ---- epilogue: dump logits to smem, per-thread top-8 ----
    float* lg = (float*)(smem + SM_BASE);
    #pragma unroll
    for (int mi = 0; mi < 2; mi++)
        #pragma unroll
        for (int j = 0; j < 4; j++) {
            int r  = m0 + mi*16 + (lane >> 2);
            int cc = n0 + j*8 + 2*(lane & 3);
            *(float2*)&lg[(size_t)r * LSTR + cc]       = make_float2(master[mi][j][0], master[mi][j][1]);
            *(float2*)&lg[(size_t)(r + 8) * LSTR + cc] = make_float2(master[mi][j][2], master[mi][j][3]);
        }
    __syncthreads();

    if (tid < MTILE) {
        const int row = row_base + tid;
        float tv[TOPK]; int ti[TOPK];
        #pragma unroll
        for (int t = 0; t < TOPK; t++) { tv[t] = -INFINITY; ti[t] = 0x7fffffff; }
        const float* lr = &lg[(size_t)tid * LSTR];
        for (int g = 0; g < 64; g++) {
            float4 v4 = *(const float4*)(lr + g * 4);
            float vs[4] = {v4.x, v4.y, v4.z, v4.w};
            #pragma unroll
            for (int q = 0; q < 4; q++) {
                float v = vs[q];
                if (v > tv[TOPK-1]) {
                    tv[TOPK-1] = v; ti[TOPK-1] = g*4 + q;
                    #pragma unroll
                    for (int t = TOPK-1; t > 0; t--) {
                        if (tv[t] > tv[t-1]) {
                            float fv = tv[t]; tv[t] = tv[t-1]; tv[t-1] = fv;
                            int   fi = ti[t]; ti[t] = ti[t-1]; ti[t-1] = fi;
                        }
                    }
                }
            }
        }
        // Z cancels under top-k renorm: w_t = 2.5 * exp(v_t - mx) / sum
        float e[TOPK], ssum = 0.0f;
        #pragma unroll
        for (int t = 0; t < TOPK; t++) { e[t] = expf(tv[t] - tv[0]); ssum += e[t]; }
        const float scale = 2.5f / ssum;
        const size_t base = (size_t)row * TOPK;
        const size_t wofs = (size_t)T * TOPK;
        #pragma unroll
        for (int t = 0; t < TOPK; t++) {
            out[base + t]        = (float)ti[t];
            out[wofs + base + t] = e[t] * scale;
        }
    }
}

extern "C" void kernel_launch(void* const* d_in, const int* in_sizes, int n_in,
                              void* d_out, int out_size) {
    const float* x = (const float*)d_in[0];
    const float* w = (const float*)d_in[1];
    float* out = (float*)d_out;
    int T = in_sizes[0] / HDIM;   // 16384

    cudaFuncSetAttribute(moe_gate_mma, cudaFuncAttributeMaxDynamicSharedMemorySize, SMEM_BYTES);

    wprep_kernel<<<NCHUNK, 256>>>(w);
    moe_gate_mma<<<T / MTILE, 512, SMEM_BYTES>>>(x, out, T);
}

// round 15
// speedup vs baseline: 1.9928x; 1.0522x over previous
#include <cuda_runtime.h>
#include <cuda_fp16.h>
#include <stdint.h>
#include <math.h>

#define HDIM    4096
#define NEXP    256
#define KC      32
#define NCHUNK  128
#define MTILE   32
#define TOPK    8

#define A_SP    2048                 // one A split tile: 32 rows x 64B
#define B_SP    16384                // one B split tile: 256 rows x 64B
#define A_BYTES (2*A_SP)             // 4096
#define B_BYTES (2*B_SP)             // 32768
#define STAGE   (A_BYTES + B_BYTES)  // 36864
#define SM_BASE 1024
#define SMEM_BYTES (SM_BASE + 2*STAGE)  // 74752 -> 2 CTAs/SM
#define LSTR 260

// Pre-split, pre-swizzled W (fp16 h + m*4096): [chunk32][2 splits][16KB]
__device__ __align__(128) uint8_t g_wt[(size_t)NCHUNK * B_BYTES];

__device__ __forceinline__ uint32_t smem_u32(const void* p) {
    uint32_t a;
    asm("{ .reg .u64 t; cvta.to.shared.u64 t, %1; cvt.u32.u64 %0, t; }" : "=r"(a) : "l"(p));
    return a;
}
__device__ __forceinline__ uint32_t swz64(uint32_t o) { return o ^ ((o >> 3) & 0x30); }

__device__ __forceinline__ uint32_t packh(float lo, float hi) {
    __half2 h = __floats2half2_rn(lo, hi);   // .x = lo (low 16) = even k elem
    return *(uint32_t*)&h;
}
// x = h + m*2^-12, m kept fp16-normal; residual <= ~2^-24 |x|
__device__ __forceinline__ void split2(float x0, float x1, uint32_t& h, uint32_t& m) {
    h = packh(x0, x1);
    __half2 hh = *(__half2*)&h;
    float h0 = __low2float(hh), h1 = __high2float(hh);
    m = packh((x0 - h0) * 4096.0f, (x1 - h1) * 4096.0f);
}

__device__ __forceinline__ void mbar_init(uint32_t a, uint32_t c) {
    asm volatile("mbarrier.init.shared.b64 [%0], %1;" :: "r"(a), "r"(c) : "memory");
}
__device__ __forceinline__ void mbar_expect_tx(uint32_t a, uint32_t b) {
    asm volatile("mbarrier.arrive.expect_tx.shared.b64 _, [%0], %1;" :: "r"(a), "r"(b) : "memory");
}
__device__ __forceinline__ void mbar_wait(uint32_t a, uint32_t ph) {
    uint32_t done;
    asm volatile("{\n\t.reg .pred p;\n\t"
                 "mbarrier.try_wait.parity.acquire.cta.shared::cta.b64 p, [%1], %2;\n\t"
                 "selp.b32 %0,1,0,p;\n\t}" : "=r"(done) : "r"(a), "r"(ph) : "memory");
    if (!done) {
        asm volatile("{\n\t.reg .pred P;\n"
                     "W0_%=:\n\t"
                     "mbarrier.try_wait.parity.acquire.cta.shared::cta.b64 P, [%0], %1, 0x989680;\n\t"
                     "@P bra W1_%=;\n\t"
                     "bra W0_%=;\n"
                     "W1_%=:\n\t}" :: "r"(a), "r"(ph) : "memory");
    }
}
__device__ __forceinline__ void bulk_cp(uint32_t dst, const void* src, uint32_t bytes, uint32_t mbar) {
    asm volatile("cp.async.bulk.shared::cluster.global.mbarrier::complete_tx::bytes "
                 "[%0], [%1], %2, [%3];"
                 :: "r"(dst), "l"(src), "r"(bytes), "r"(mbar) : "memory");
}

#define LDSM4(r, addr)                                                           \
    asm volatile("ldmatrix.sync.aligned.m8n8.x4.shared.b16 {%0,%1,%2,%3}, [%4];" \
        : "=r"((r)[0]), "=r"((r)[1]), "=r"((r)[2]), "=r"((r)[3]) : "r"(addr))

#define MMA_ACC(c, a, b0v, b1v)                                                  \
    asm volatile("mma.sync.aligned.m16n8k16.row.col.f32.f16.f16.f32 "            \
        "{%0,%1,%2,%3}, {%4,%5,%6,%7}, {%8,%9}, {%0,%1,%2,%3};"                  \
        : "+f"((c)[0]), "+f"((c)[1]), "+f"((c)[2]), "+f"((c)[3])                 \
        : "r"((a)[0]), "r"((a)[1]), "r"((a)[2]), "r"((a)[3]), "r"(b0v), "r"(b1v))

#define MMA_NEW(c, a, b0v, b1v)                                                  \
    asm volatile("mma.sync.aligned.m16n8k16.row.col.f32.f16.f16.f32 "            \
        "{%0,%1,%2,%3}, {%4,%5,%6,%7}, {%8,%9}, {%10,%10,%10,%10};"              \
        : "=f"((c)[0]), "=f"((c)[1]), "=f"((c)[2]), "=f"((c)[3])                 \
        : "r"((a)[0]), "r"((a)[1]), "r"((a)[2]), "r"((a)[3]), "r"(b0v), "r"(b1v),\
          "f"(0.0f))

// ---------------- W pre-split kernel: grid=128 k32-chunks, 256 thr = experts ---
__global__ void __launch_bounds__(256) wprep_kernel(const float* __restrict__ w) {
    const int c = blockIdx.x;
    const int e = threadIdx.x;
    const float4* src = (const float4*)(w + (size_t)e * HDIM + c * KC);
    float xv[32];
    #pragma unroll
    for (int i = 0; i < 8; i++) {
        float4 f = src[i];
        xv[i*4+0]=f.x; xv[i*4+1]=f.y; xv[i*4+2]=f.z; xv[i*4+3]=f.w;
    }
    uint32_t hh[16], mm_[16];
    #pragma unroll
    for (int j = 0; j < 16; j++) split2(xv[2*j], xv[2*j+1], hh[j], mm_[j]);
    uint8_t* base = g_wt + (size_t)c * B_BYTES;
    #pragma unroll
    for (int b = 0; b < 4; b++) {
        uint32_t so = swz64((uint32_t)e * 64 + b * 16);
        *(uint4*)(base + 0*B_SP + so) = make_uint4(hh[4*b],hh[4*b+1],hh[4*b+2],hh[4*b+3]);
        *(uint4*)(base + 1*B_SP + so) = make_uint4(mm_[4*b],mm_[4*b+1],mm_[4*b+2],mm_[4*b+3]);
    }
}

// ------ main kernel: grid = T/32, 128 threads (4 warps, tile 32x64), 2 CTAs/SM -
__global__ void __launch_bounds__(128, 2)
moe_gate_mma(const float* __restrict__ x, float* __restrict__ out, int T) {
    extern __shared__ __align__(1024) uint8_t smem[];
    const uint32_t sbase = smem_u32(smem);
    const int tid  = threadIdx.x;
    const int wid  = tid >> 5;
    const int lane = tid & 31;
    const int row_base = blockIdx.x * MTILE;

    if (tid == 0) { mbar_init(sbase + 16, 1); mbar_init(sbase + 24, 1); }

    // A staging: thread -> row = tid/4 (0..31), 8 fp32 k-elems at (tid%4)*8
    const int arow = tid >> 2;
    const int aq   = tid & 3;
    const float* xrow = x + (size_t)(row_base + arow) * HDIM + aq * 8;
    const uint32_t a_sts = swz64((uint32_t)arow * 64 + aq * 16);

    // warp tile: 32M x 64N  (4 warps = 1M x 4N); m0 = 0 for all warps
    const int n0 = wid * 64;

    // swizzled ldmatrix offsets (k-step offset added BEFORE swizzle)
    uint32_t aoff[2][2], boff[2][4];
    {
        uint32_t a_row = (uint32_t)(lane & 15);
        uint32_t a_kh  = (uint32_t)(lane >> 4) * 16;
        uint32_t b_n   = (uint32_t)(n0 + (lane & 7) + ((lane >> 4) & 1) * 8);
        uint32_t b_kh  = (uint32_t)((lane >> 3) & 1) * 16;
        #pragma unroll
        for (int ks = 0; ks < 2; ks++) {
            #pragma unroll
            for (int mi = 0; mi < 2; mi++)
                aoff[ks][mi] = swz64((a_row + mi*16) * 64 + ks*32 + a_kh);
            #pragma unroll
            for (int nb = 0; nb < 4; nb++)
                boff[ks][nb] = swz64((b_n + nb*16) * 64 + ks*32 + b_kh);
        }
    }

    float master[2][8][4];   // fp32-RN sum of hh products (64 regs)
    float winc[2][8][4];     // hm+mh persistent chained window, x4096 (64 regs)
    #pragma unroll
    for (int mi = 0; mi < 2; mi++)
        #pragma unroll
        for (int j = 0; j < 8; j++)
            #pragma unroll
            for (int q = 0; q < 4; q++)
                { master[mi][j][q] = 0.0f; winc[mi][j][q] = 0.0f; }

    __syncthreads();   // mbarriers visible

    // prologue: stage chunk 0, prefetch x chunk 1
    if (tid == 0) {
        mbar_expect_tx(sbase + 16, B_BYTES);
        bulk_cp(sbase + SM_BASE + A_BYTES, g_wt, B_BYTES, sbase + 16);
    }
    {
        float4 f0 = *(const float4*)(xrow);
        float4 f1 = *(const float4*)(xrow + 4);
        uint32_t h[4], m[4];
        split2(f0.x, f0.y, h[0], m[0]); split2(f0.z, f0.w, h[1], m[1]);
        split2(f1.x, f1.y, h[2], m[2]); split2(f1.z, f1.w, h[3], m[3]);
        *(uint4*)(smem + SM_BASE + 0*A_SP + a_sts) = make_uint4(h[0],h[1],h[2],h[3]);
        *(uint4*)(smem + SM_BASE + 1*A_SP + a_sts) = make_uint4(m[0],m[1],m[2],m[3]);
    }
    float4 xp0 = *(const float4*)(xrow + KC);
    float4 xp1 = *(const float4*)(xrow + KC + 4);
    __syncthreads();

    for (int i = 0; i < NCHUNK; i++) {
        const int s = i & 1;
        const uint32_t stoff = SM_BASE + (uint32_t)s * STAGE;

        mbar_wait(sbase + 16 + 8*s, (i >> 1) & 1);

        if (i < NCHUNK - 1) {
            const uint32_t nstoff = SM_BASE + (uint32_t)(s ^ 1) * STAGE;
            if (tid == 0) {
                mbar_expect_tx(sbase + 16 + 8*(s^1), B_BYTES);
                bulk_cp(sbase + nstoff + A_BYTES, g_wt + (size_t)(i+1) * B_BYTES,
                        B_BYTES, sbase + 16 + 8*(s^1));
            }
            uint32_t h[4], m[4];
            split2(xp0.x, xp0.y, h[0], m[0]); split2(xp0.z, xp0.w, h[1], m[1]);
            split2(xp1.x, xp1.y, h[2], m[2]); split2(xp1.z, xp1.w, h[3], m[3]);
            *(uint4*)(smem + nstoff + 0*A_SP + a_sts) = make_uint4(h[0],h[1],h[2],h[3]);
            *(uint4*)(smem + nstoff + 1*A_SP + a_sts) = make_uint4(m[0],m[1],m[2],m[3]);
            if (i < NCHUNK - 2) {
                xp0 = *(const float4*)(xrow + (size_t)(i+2) * KC);
                xp1 = *(const float4*)(xrow + (size_t)(i+2) * KC + 4);
            }
        }

        // ---- compute chunk i: 2 k16 steps (per-element order: hh, mh, hm) ----
        const uint32_t Ab = sbase + stoff;
        const uint32_t Bb = sbase + stoff + A_BYTES;
        #pragma unroll
        for (int ks = 0; ks < 2; ks++) {
            uint32_t Bf[4][4], Ah[2][4], Am[2][4];
            #pragma unroll
            for (int nb = 0; nb < 4; nb++) LDSM4(Bf[nb], Bb + boff[ks][nb]);   // B_h
            #pragma unroll
            for (int mi = 0; mi < 2; mi++) LDSM4(Ah[mi], Ab + aoff[ks][mi]);
            #pragma unroll
            for (int mi = 0; mi < 2; mi++) LDSM4(Am[mi], Ab + A_SP + aoff[ks][mi]);

            // hh: fresh C per MMA, immediate fp32-RN drain (wh scratch 32 regs)
            #pragma unroll
            for (int mi = 0; mi < 2; mi++) {
                float wh[8][4];
                #pragma unroll
                for (int nb = 0; nb < 4; nb++) {
                    MMA_NEW(wh[nb*2+0], Ah[mi], Bf[nb][0], Bf[nb][1]);
                    MMA_NEW(wh[nb*2+1], Ah[mi], Bf[nb][2], Bf[nb][3]);
                }
                #pragma unroll
                for (int j = 0; j < 8; j++)
                    #pragma unroll
                    for (int q = 0; q < 4; q++)
                        master[mi][j][q] += wh[j][q];
            }
            // mh: A_m x B_h into persistent chained window
            #pragma unroll
            for (int mi = 0; mi < 2; mi++)
                #pragma unroll
                for (int nb = 0; nb < 4; nb++) {
                    MMA_ACC(winc[mi][nb*2+0], Am[mi], Bf[nb][0], Bf[nb][1]);
                    MMA_ACC(winc[mi][nb*2+1], Am[mi], Bf[nb][2], Bf[nb][3]);
                }
            // hm: B_m reuses Bf regs (B_h dead)
            #pragma unroll
            for (int nb = 0; nb < 4; nb++) LDSM4(Bf[nb], Bb + B_SP + boff[ks][nb]);
            #pragma unroll
            for (int mi = 0; mi < 2; mi++)
                #pragma unroll
                for (int nb = 0; nb < 4; nb++) {
                    MMA_ACC(winc[mi][nb*2+0], Ah[mi], Bf[nb][0], Bf[nb][1]);
                    MMA_ACC(winc[mi][nb*2+1], Ah[mi], Bf[nb][2], Bf[nb][3]);
                }
        }
        __syncthreads();
    }

    // combine: logits = master + winc * 2^-12 (single final fold)
    const float CS = 1.0f / 4096.0f;
    #pragma unroll
    for (int mi = 0; mi < 2; mi++)
        #pragma unroll
        for (int j = 0; j < 8; j++)
            #pragma unroll
            for (int q = 0; q < 4; q++)
                master[mi][j][q] = fmaf(winc[mi][j][q], CS, master[mi][j][q]);

    // ---- epilogue: dump logits to smem, per-thread top-8 ----
    float* lg = (float*)(smem + SM_BASE);
    #pragma unroll
    for (int mi = 0; mi < 2; mi++)
        #pragma unroll
        for (int j = 0; j < 8; j++) {
            int r  = mi*16 + (lane >> 2);
            int cc = n0 + j*8 + 2*(lane & 3);
            *(float2*)&lg[(size_t)r * LSTR + cc]       = make_float2(master[mi][j][0], master[mi][j][1]);
            *(float2*)&lg[(size_t)(r + 8) * LSTR + cc] = make_float2(master[mi][j][2], master[mi][j][3]);
        }
    __syncthreads();

    if (tid < MTILE) {
        const int row = row_base + tid;
        float tv[TOPK]; int ti[TOPK];
        #pragma unroll
        for (int t = 0; t < TOPK; t++) { tv[t] = -INFINITY; ti[t] = 0x7fffffff; }
        const float* lr = &lg[(size_t)tid * LSTR];
        for (int g = 0; g < 64; g++) {
            float4 v4 = *(const float4*)(lr + g * 4);
            float vs[4] = {v4.x, v4.y, v4.z, v4.w};
            #pragma unroll
            for (int q = 0; q < 4; q++) {
                float v = vs[q];
                if (v > tv[TOPK-1]) {
                    tv[TOPK-1] = v; ti[TOPK-1] = g*4 + q;
                    #pragma unroll
                    for (int t = TOPK-1; t > 0; t--) {
                        if (tv[t] > tv[t-1]) {
                            float fv = tv[t]; tv[t] = tv[t-1]; tv[t-1] = fv;
                            int   fi = ti[t]; ti[t] = ti[t-1]; ti[t-1] = fi;
                        }
                    }
                }
            }
        }
        // Z cancels under top-k renorm: w_t = 2.5 * exp(v_t - mx) / sum
        float e[TOPK], ssum = 0.0f;
        #pragma unroll
        for (int t = 0; t < TOPK; t++) { e[t] = expf(tv[t] - tv[0]); ssum += e[t]; }
        const float scale = 2.5f / ssum;
        const size_t base = (size_t)row * TOPK;
        const size_t wofs = (size_t)T * TOPK;
        #pragma unroll
        for (int t = 0; t < TOPK; t++) {
            out[base + t]        = (float)ti[t];
            out[wofs + base + t] = e[t] * scale;
        }
    }
}

extern "C" void kernel_launch(void* const* d_in, const int* in_sizes, int n_in,
                              void* d_out, int out_size) {
    const float* x = (const float*)d_in[0];
    const float* w = (const float*)d_in[1];
    float* out = (float*)d_out;
    int T = in_sizes[0] / HDIM;   // 16384

    cudaFuncSetAttribute(moe_gate_mma, cudaFuncAttributeMaxDynamicSharedMemorySize, SMEM_BYTES);

    wprep_kernel<<<NCHUNK, 256>>>(w);
    moe_gate_mma<<<T / MTILE, 128, SMEM_BYTES>>>(x, out, T);
}

// round 16
// speedup vs baseline: 2.1029x; 1.0553x over previous
#include <cuda_runtime.h>
#include <cuda_fp16.h>
#include <stdint.h>
#include <math.h>

#define HDIM   4096
#define NEXP   256
#define KC     64
#define NCHUNK 64
#define MTILE  64
#define TOPK   8

#define A_SP    8192                 // one A split tile: 64 rows x 128B
#define B_SP    32768                // one B split tile: 256 rows x 128B
#define A_BYTES (2*A_SP)             // 16384
#define B_BYTES (2*B_SP)             // 65536
#define STAGE   (A_BYTES + B_BYTES)  // 81920
#define SM_BASE 1024
#define SMEM_BYTES (SM_BASE + 2*STAGE)  // 164864
#define LSTR 260

// Pre-split, pre-swizzled W (fp16 h + m*4096): [chunk64][2 splits][32KB]
__device__ __align__(128) uint8_t g_wt[(size_t)NCHUNK * B_BYTES];

__device__ __forceinline__ uint32_t smem_u32(const void* p) {
    uint32_t a;
    asm("{ .reg .u64 t; cvta.to.shared.u64 t, %1; cvt.u32.u64 %0, t; }" : "=r"(a) : "l"(p));
    return a;
}
// SW128: row*128 + col  ->  col bits [6:4] ^= row bits [2:0]
__device__ __forceinline__ uint32_t swz128(uint32_t o) { return o ^ ((o >> 3) & 0x70); }

__device__ __forceinline__ uint32_t packh(float lo, float hi) {
    __half2 h = __floats2half2_rn(lo, hi);   // .x = lo (low 16) = elem k
    return *(uint32_t*)&h;
}
// x = h + m*2^-12, both fp16-normal range; residual <= ~2^-24 |x|
__device__ __forceinline__ void split2(float x0, float x1, uint32_t& h, uint32_t& m) {
    h = packh(x0, x1);
    __half2 hh = *(__half2*)&h;
    float h0 = __low2float(hh), h1 = __high2float(hh);
    m = packh((x0 - h0) * 4096.0f, (x1 - h1) * 4096.0f);
}

__device__ __forceinline__ void mbar_init(uint32_t a, uint32_t c) {
    asm volatile("mbarrier.init.shared.b64 [%0], %1;" :: "r"(a), "r"(c) : "memory");
}
__device__ __forceinline__ void mbar_expect_tx(uint32_t a, uint32_t b) {
    asm volatile("mbarrier.arrive.expect_tx.shared.b64 _, [%0], %1;" :: "r"(a), "r"(b) : "memory");
}
__device__ __forceinline__ void mbar_wait(uint32_t a, uint32_t ph) {
    uint32_t done;
    asm volatile("{\n\t.reg .pred p;\n\t"
                 "mbarrier.try_wait.parity.acquire.cta.shared::cta.b64 p, [%1], %2;\n\t"
                 "selp.b32 %0,1,0,p;\n\t}" : "=r"(done) : "r"(a), "r"(ph) : "memory");
    if (!done) {
        asm volatile("{\n\t.reg .pred P;\n"
                     "W0_%=:\n\t"
                     "mbarrier.try_wait.parity.acquire.cta.shared::cta.b64 P, [%0], %1, 0x989680;\n\t"
                     "@P bra W1_%=;\n\t"
                     "bra W0_%=;\n"
                     "W1_%=:\n\t}" :: "r"(a), "r"(ph) : "memory");
    }
}
__device__ __forceinline__ void bulk_cp(uint32_t dst, const void* src, uint32_t bytes, uint32_t mbar) {
    asm volatile("cp.async.bulk.shared::cluster.global.mbarrier::complete_tx::bytes "
                 "[%0], [%1], %2, [%3];"
                 :: "r"(dst), "l"(src), "r"(bytes), "r"(mbar) : "memory");
}

#define LDSM4(r, addr)                                                           \
    asm volatile("ldmatrix.sync.aligned.m8n8.x4.shared.b16 {%0,%1,%2,%3}, [%4];" \
        : "=r"((r)[0]), "=r"((r)[1]), "=r"((r)[2]), "=r"((r)[3]) : "r"(addr))

// chained accumulate: c += a*b
#define MMA_ACC(c, a, b0v, b1v)                                                  \
    asm volatile("mma.sync.aligned.m16n8k16.row.col.f32.f16.f16.f32 "            \
        "{%0,%1,%2,%3}, {%4,%5,%6,%7}, {%8,%9}, {%0,%1,%2,%3};"                  \
        : "+f"((c)[0]), "+f"((c)[1]), "+f"((c)[2]), "+f"((c)[3])                 \
        : "r"((a)[0]), "r"((a)[1]), "r"((a)[2]), "r"((a)[3]), "r"(b0v), "r"(b1v))

// fresh window: c = a*b + 0
#define MMA_NEW(c, a, b0v, b1v)                                                  \
    asm volatile("mma.sync.aligned.m16n8k16.row.col.f32.f16.f16.f32 "            \
        "{%0,%1,%2,%3}, {%4,%5,%6,%7}, {%8,%9}, {%10,%10,%10,%10};"              \
        : "=f"((c)[0]), "=f"((c)[1]), "=f"((c)[2]), "=f"((c)[3])                 \
        : "r"((a)[0]), "r"((a)[1]), "r"((a)[2]), "r"((a)[3]), "r"(b0v), "r"(b1v),\
          "f"(0.0f))

// ---------------- W pre-split kernel: grid=128 k32-chunks, 256 thr = experts ---
__global__ void __launch_bounds__(256) wprep_kernel(const float* __restrict__ w) {
    const int c32 = blockIdx.x;            // 0..127 (32-wide k chunks)
    const int e   = threadIdx.x;
    const int c64 = c32 >> 1;
    const int kh  = (c32 & 1) * 64;        // byte offset within 128B row
    const float4* src = (const float4*)(w + (size_t)e * HDIM + c32 * 32);
    float xv[32];
    #pragma unroll
    for (int i = 0; i < 8; i++) {
        float4 f = src[i];
        xv[i*4+0]=f.x; xv[i*4+1]=f.y; xv[i*4+2]=f.z; xv[i*4+3]=f.w;
    }
    uint32_t hh[16], mm_[16];
    #pragma unroll
    for (int j = 0; j < 16; j++) split2(xv[2*j], xv[2*j+1], hh[j], mm_[j]);
    uint8_t* base = g_wt + (size_t)c64 * B_BYTES;
    #pragma unroll
    for (int b = 0; b < 4; b++) {
        uint32_t so = swz128((uint32_t)e * 128 + kh + b * 16);
        *(uint4*)(base + 0*B_SP + so) = make_uint4(hh[4*b],hh[4*b+1],hh[4*b+2],hh[4*b+3]);
        *(uint4*)(base + 1*B_SP + so) = make_uint4(mm_[4*b],mm_[4*b+1],mm_[4*b+2],mm_[4*b+3]);
    }
}

// ---------------- main kernel: grid = T/64, 256 threads (8 warps 2Mx4N) --------
__global__ void __launch_bounds__(256, 1)
moe_gate_mma(const float* __restrict__ x, float* __restrict__ out, int T) {
    extern __shared__ __align__(1024) uint8_t smem[];
    const uint32_t sbase = smem_u32(smem);
    const int tid  = threadIdx.x;
    const int wid  = tid >> 5;
    const int lane = tid & 31;
    const int row_base = blockIdx.x * MTILE;

    if (tid == 0) { mbar_init(sbase + 16, 1); mbar_init(sbase + 24, 1); }

    // A staging: thread -> row = tid/4 (0..63), 16 k-elems at (tid%4)*16
    const int arow = tid >> 2;
    const int aq   = tid & 3;
    const float* xrow = x + (size_t)(row_base + arow) * HDIM + aq * 16;
    const uint32_t a_sts0 = swz128((uint32_t)arow * 128 + aq * 32);
    const uint32_t a_sts1 = swz128((uint32_t)arow * 128 + aq * 32 + 16);

    // warp tile: 32M x 64N  (8 warps = 2M x 4N)
    const int wm = wid & 1, wn = wid >> 1;
    const int m0 = wm * 32, n0 = wn * 64;

    // swizzled ldmatrix offsets: ks in 0..3 (k16 steps within KC=64)
    uint32_t aoff[4][2], boff[4][4];
    {
        uint32_t a_row = (uint32_t)(m0 + (lane & 15));
        uint32_t a_kh  = (uint32_t)(lane >> 4) * 16;
        uint32_t b_n   = (uint32_t)(n0 + (lane & 7) + ((lane >> 4) & 1) * 8);
        uint32_t b_kh  = (uint32_t)((lane >> 3) & 1) * 16;
        #pragma unroll
        for (int ks = 0; ks < 4; ks++) {
            #pragma unroll
            for (int mi = 0; mi < 2; mi++)
                aoff[ks][mi] = swz128((a_row + mi*16) * 128 + ks*32 + a_kh);
            #pragma unroll
            for (int nb = 0; nb < 4; nb++)
                boff[ks][nb] = swz128((b_n + nb*16) * 128 + ks*32 + b_kh);
        }
    }

    float master[2][8][4];   // fp32-RN sum of hh windows
    float winc[2][8][4];     // hm+mh window, chained ALL chunks, scaled 2^12
    #pragma unroll
    for (int mi = 0; mi < 2; mi++)
        #pragma unroll
        for (int j = 0; j < 8; j++)
            #pragma unroll
            for (int q = 0; q < 4; q++)
                { master[mi][j][q] = 0.0f; winc[mi][j][q] = 0.0f; }

    __syncthreads();   // mbarriers visible

    // prologue: stage chunk 0 (A split + TMA B), prefetch x chunk 1
    if (tid == 0) {
        mbar_expect_tx(sbase + 16, B_BYTES);
        bulk_cp(sbase + SM_BASE + A_BYTES, g_wt, B_BYTES, sbase + 16);
    }
    {
        float4 f0 = *(const float4*)(xrow);
        float4 f1 = *(const float4*)(xrow + 4);
        float4 f2 = *(const float4*)(xrow + 8);
        float4 f3 = *(const float4*)(xrow + 12);
        uint32_t h[8], m[8];
        split2(f0.x, f0.y, h[0], m[0]); split2(f0.z, f0.w, h[1], m[1]);
        split2(f1.x, f1.y, h[2], m[2]); split2(f1.z, f1.w, h[3], m[3]);
        split2(f2.x, f2.y, h[4], m[4]); split2(f2.z, f2.w, h[5], m[5]);
        split2(f3.x, f3.y, h[6], m[6]); split2(f3.z, f3.w, h[7], m[7]);
        *(uint4*)(smem + SM_BASE + 0*A_SP + a_sts0) = make_uint4(h[0],h[1],h[2],h[3]);
        *(uint4*)(smem + SM_BASE + 0*A_SP + a_sts1) = make_uint4(h[4],h[5],h[6],h[7]);
        *(uint4*)(smem + SM_BASE + 1*A_SP + a_sts0) = make_uint4(m[0],m[1],m[2],m[3]);
        *(uint4*)(smem + SM_BASE + 1*A_SP + a_sts1) = make_uint4(m[4],m[5],m[6],m[7]);
    }
    float4 xr0 = *(const float4*)(xrow + KC);
    float4 xr1 = *(const float4*)(xrow + KC + 4);
    float4 xr2 = *(const float4*)(xrow + KC + 8);
    float4 xr3 = *(const float4*)(xrow + KC + 12);
    __syncthreads();

    for (int i = 0; i < NCHUNK; i++) {
        const int s = i & 1;
        const uint32_t stoff = SM_BASE + (uint32_t)s * STAGE;

        mbar_wait(sbase + 16 + 8*s, (i >> 1) & 1);

        if (i < NCHUNK - 1) {
            const uint32_t nstoff = SM_BASE + (uint32_t)(s ^ 1) * STAGE;
            if (tid == 0) {
                mbar_expect_tx(sbase + 16 + 8*(s^1), B_BYTES);
                bulk_cp(sbase + nstoff + A_BYTES, g_wt + (size_t)(i+1) * B_BYTES,
                        B_BYTES, sbase + 16 + 8*(s^1));
            }
            uint32_t h[8], m[8];
            split2(xr0.x, xr0.y, h[0], m[0]); split2(xr0.z, xr0.w, h[1], m[1]);
            split2(xr1.x, xr1.y, h[2], m[2]); split2(xr1.z, xr1.w, h[3], m[3]);
            split2(xr2.x, xr2.y, h[4], m[4]); split2(xr2.z, xr2.w, h[5], m[5]);
            split2(xr3.x, xr3.y, h[6], m[6]); split2(xr3.z, xr3.w, h[7], m[7]);
            *(uint4*)(smem + nstoff + 0*A_SP + a_sts0) = make_uint4(h[0],h[1],h[2],h[3]);
            *(uint4*)(smem + nstoff + 0*A_SP + a_sts1) = make_uint4(h[4],h[5],h[6],h[7]);
            *(uint4*)(smem + nstoff + 1*A_SP + a_sts0) = make_uint4(m[0],m[1],m[2],m[3]);
            *(uint4*)(smem + nstoff + 1*A_SP + a_sts1) = make_uint4(m[4],m[5],m[6],m[7]);
            if (i < NCHUNK - 2) {
                xr0 = *(const float4*)(xrow + (size_t)(i+2) * KC);
                xr1 = *(const float4*)(xrow + (size_t)(i+2) * KC + 4);
                xr2 = *(const float4*)(xrow + (size_t)(i+2) * KC + 8);
                xr3 = *(const float4*)(xrow + (size_t)(i+2) * KC + 12);
            }
        }

        // ---- compute chunk i: 4 k16 steps, products hh (drained), mh+hm (chained) ----
        const uint32_t Ab = sbase + stoff;
        const uint32_t Bb = sbase + stoff + A_BYTES;
        #pragma unroll
        for (int ks = 0; ks < 4; ks++) {
            uint32_t Bf[4][4], Ah[2][4], Am[2][4];
            #pragma unroll
            for (int nb = 0; nb < 4; nb++)
                LDSM4(Bf[nb], Bb + boff[ks][nb]);            // B_h
            #pragma unroll
            for (int mi = 0; mi < 2; mi++)
                LDSM4(Ah[mi], Ab + aoff[ks][mi]);            // A_h
            #pragma unroll
            for (int mi = 0; mi < 2; mi++)
                LDSM4(Am[mi], Ab + A_SP + aoff[ks][mi]);     // A_m

            // hh: fresh C per MMA, drain in fp32 RN
            #pragma unroll
            for (int mi = 0; mi < 2; mi++) {
                float wh[8][4];
                #pragma unroll
                for (int nb = 0; nb < 4; nb++) {
                    MMA_NEW(wh[nb*2+0], Ah[mi], Bf[nb][0], Bf[nb][1]);
                    MMA_NEW(wh[nb*2+1], Ah[mi], Bf[nb][2], Bf[nb][3]);
                }
                #pragma unroll
                for (int j = 0; j < 8; j++)
                    #pragma unroll
                    for (int q = 0; q < 4; q++)
                        master[mi][j][q] += wh[j][q];
            }
            // mh: A_m x B_h into chained window
            #pragma unroll
            for (int mi = 0; mi < 2; mi++)
                #pragma unroll
                for (int nb = 0; nb < 4; nb++) {
                    MMA_ACC(winc[mi][nb*2+0], Am[mi], Bf[nb][0], Bf[nb][1]);
                    MMA_ACC(winc[mi][nb*2+1], Am[mi], Bf[nb][2], Bf[nb][3]);
                }
            // hm: load B_m (reuse Bf), A_h x B_m into chained window
            #pragma unroll
            for (int nb = 0; nb < 4; nb++)
                LDSM4(Bf[nb], Bb + B_SP + boff[ks][nb]);
            #pragma unroll
            for (int mi = 0; mi < 2; mi++)
                #pragma unroll
                for (int nb = 0; nb < 4; nb++) {
                    MMA_ACC(winc[mi][nb*2+0], Ah[mi], Bf[nb][0], Bf[nb][1]);
                    MMA_ACC(winc[mi][nb*2+1], Ah[mi], Bf[nb][2], Bf[nb][3]);
                }
        }
        __syncthreads();
    }

    // combine: logits = master + winc * 2^-12
    const float CS = 1.0f / 4096.0f;
    #pragma unroll
    for (int mi = 0; mi < 2; mi++)
        #pragma unroll
        for (int j = 0; j < 8; j++)
            #pragma unroll
            for (int q = 0; q < 4; q++)
                master[mi][j][q] = fmaf(winc[mi][j][q], CS, master[mi][j][q]);

    // ---- epilogue: dump logits to smem, per-thread top-8 ----
    float* lg = (float*)(smem + SM_BASE);
    #pragma unroll
    for (int mi = 0; mi < 2; mi++)
        #pragma unroll
        for (int j = 0; j < 8; j++) {
            int r = m0 + mi*16 + (lane >> 2);
            int c = n0 + j*8 + 2*(lane & 3);
            *(float2*)&lg[(size_t)r * LSTR + c]       = make_float2(master[mi][j][0], master[mi][j][1]);
            *(float2*)&lg[(size_t)(r + 8) * LSTR + c] = make_float2(master[mi][j][2], master[mi][j][3]);
        }
    __syncthreads();

    if (tid < MTILE) {
        const int row = row_base + tid;
        float tv[TOPK]; int ti[TOPK];
        #pragma unroll
        for (int t = 0; t < TOPK; t++) { tv[t] = -INFINITY; ti[t] = 0x7fffffff; }
        const float* lr = &lg[(size_t)tid * LSTR];
        for (int g = 0; g < 64; g++) {
            float4 v4 = *(const float4*)(lr + g * 4);
            float vs[4] = {v4.x, v4.y, v4.z, v4.w};
            #pragma unroll
            for (int q = 0; q < 4; q++) {
                float v = vs[q];
                if (v > tv[TOPK-1]) {
                    tv[TOPK-1] = v; ti[TOPK-1] = g*4 + q;
                    #pragma unroll
                    for (int t = TOPK-1; t > 0; t--) {
                        if (tv[t] > tv[t-1]) {
                            float fv = tv[t]; tv[t] = tv[t-1]; tv[t-1] = fv;
                            int   fi = ti[t]; ti[t] = ti[t-1]; ti[t-1] = fi;
                        }
                    }
                }
            }
        }
        // Z cancels under top-k renorm: w_t = 2.5 * exp(v_t - mx) / sum
        float e[TOPK], ssum = 0.0f;
        #pragma unroll
        for (int t = 0; t < TOPK; t++) { e[t] = expf(tv[t] - tv[0]); ssum += e[t]; }
        const float scale = 2.5f / ssum;
        const size_t base = (size_t)row * TOPK;
        const size_t wofs = (size_t)T * TOPK;
        #pragma unroll
        for (int t = 0; t < TOPK; t++) {
            out[base + t]        = (float)ti[t];
            out[wofs + base + t] = e[t] * scale;
        }
    }
}

extern "C" void kernel_launch(void* const* d_in, const int* in_sizes, int n_in,
                              void* d_out, int out_size) {
    const float* x = (const float*)d_in[0];
    const float* w = (const float*)d_in[1];
    float* out = (float*)d_out;
    int T = in_sizes[0] / HDIM;   // 16384

    cudaFuncSetAttribute(moe_gate_mma, cudaFuncAttributeMaxDynamicSharedMemorySize, SMEM_BYTES);

    wprep_kernel<<<128, 256>>>(w);
    moe_gate_mma<<<T / MTILE, 256, SMEM_BYTES>>>(x, out, T);
}